// round 15
// baseline (speedup 1.0000x reference)
#include <cuda_runtime.h>
#include <cuda_fp16.h>
#include <cstdint>

#define B_ 8
#define D_ 128
#define N_ 2048
#define BM 128
#define BN 128
#define NITER (N_ / BN)

__device__ __align__(16) __half g_Qh[B_ * D_ * N_];  // [b][d][n]
__device__ __align__(16) __half g_Vh[B_ * D_ * N_];  // [b][v][n]
__device__ int g_flags[B_ * 16];                     // slice-ready flags

__device__ __forceinline__ uint32_t s2u(const void* p) {
    uint32_t a;
    asm("{ .reg .u64 t; cvta.to.shared.u64 t, %1; cvt.u32.u64 %0, t; }" : "=r"(a) : "l"(p));
    return a;
}

#define CPA16(dst, src) \
    asm volatile("cp.async.cg.shared.global [%0], [%1], 16;" :: "r"(dst), "l"(src))
#define CPA_COMMIT() asm volatile("cp.async.commit_group;" ::: "memory")
#define CPA_WAIT0()  asm volatile("cp.async.wait_group 0;" ::: "memory")

__device__ __forceinline__ void ldmx4(uint32_t* r, uint32_t addr) {
    asm volatile("ldmatrix.sync.aligned.m8n8.x4.shared.b16 {%0,%1,%2,%3}, [%4];"
        : "=r"(r[0]), "=r"(r[1]), "=r"(r[2]), "=r"(r[3]) : "r"(addr));
}
__device__ __forceinline__ void ldmx4t(uint32_t* r, uint32_t addr) {
    asm volatile("ldmatrix.sync.aligned.m8n8.x4.trans.shared.b16 {%0,%1,%2,%3}, [%4];"
        : "=r"(r[0]), "=r"(r[1]), "=r"(r[2]), "=r"(r[3]) : "r"(addr));
}
// f32-accumulate (MMA2: K-depth 2048 needs fp32)
__device__ __forceinline__ void mma16816(float* d, const uint32_t* a, const uint32_t* b) {
    asm volatile("mma.sync.aligned.m16n8k16.row.col.f32.f16.f16.f32 "
        "{%0,%1,%2,%3}, {%4,%5,%6,%7}, {%8,%9}, {%0,%1,%2,%3};"
        : "+f"(d[0]), "+f"(d[1]), "+f"(d[2]), "+f"(d[3])
        : "r"(a[0]), "r"(a[1]), "r"(a[2]), "r"(a[3]), "r"(b[0]), "r"(b[1]));
}
// f16-accumulate (MMA1: K-depth 128, pre-scaled operands keep accumulator small)
__device__ __forceinline__ void mma16816h(uint32_t* d, const uint32_t* a, const uint32_t* b) {
    asm volatile("mma.sync.aligned.m16n8k16.row.col.f16.f16.f16.f16 "
        "{%0,%1}, {%2,%3,%4,%5}, {%6,%7}, {%0,%1};"
        : "+r"(d[0]), "+r"(d[1])
        : "r"(a[0]), "r"(a[1]), "r"(a[2]), "r"(a[3]), "r"(b[0]), "r"(b[1]));
}

// K pre-scaled by 0.5/sqrt(128): sigmoid(S/sqrt(128)) = 0.5*tanh(x)+0.5
__device__ __forceinline__ float sigf(float x) {
    float t;
    asm("tanh.approx.f32 %0, %1;" : "=f"(t) : "f"(x));
    return fmaf(t, 0.5f, 0.5f);
}
__device__ __forceinline__ uint32_t packh2(float a, float b) {
    uint32_t r;
    asm("cvt.rn.f16x2.f32 %0, %1, %2;" : "=r"(r) : "f"(b), "f"(a));
    return r;
}
__device__ __forceinline__ float2 uph2(uint32_t u) {
    __half2 h = *reinterpret_cast<__half2*>(&u);
    return __half22float2(h);
}

// smem: K 32KB @0 | Q[2] 64KB @32K | V[2] 64KB @96K
#define SM_K 0
#define SM_Q 32768
#define SM_V 98304
#define SMEM_TOTAL 163840

__global__ __launch_bounds__(256, 1)
void sigattn_hmma(const float* __restrict__ Qf, const float* __restrict__ Kf,
                  const float* __restrict__ Vf, float* __restrict__ O) {
    extern __shared__ char sm[];
    const uint32_t sb = s2u(sm);
    const int tid = threadIdx.x, w = tid >> 5, lane = tid & 31;
    const int b = blockIdx.y, bx = blockIdx.x, m0 = bx * BM;
    const int g = lane >> 3, sx = lane & 7;

    // ---- convert OWN Q,V n-slice (slice index = bx) fp32 -> fp16 global ----
    {
        const int n0c = bx * 128;
#pragma unroll
        for (int r = 0; r < 16; r++) {
            int i = tid + r * 256;          // 0..4095
            int d = i >> 5, c = i & 31;     // 128 rows x 32 float4
            const size_t base = (size_t)(b * D_ + d) * N_ + n0c;
            float4 q = *(const float4*)(Qf + base + c * 4);
            float4 v = *(const float4*)(Vf + base + c * 4);
            ((uint2*)(g_Qh + base))[c] = make_uint2(packh2(q.x, q.y), packh2(q.z, q.w));
            ((uint2*)(g_Vh + base))[c] = make_uint2(packh2(v.x, v.y), packh2(v.z, v.w));
        }
    }
    __threadfence();
    if (tid == 0) atomicExch(&g_flags[b * 16 + bx], 1);

    // ---- K tile converted in-kernel (one-time, scaled by 0.5/sqrt(128)) ----
    {
        const float C2 = 0.5f * 0.08838834764831845f;
#pragma unroll
        for (int r = 0; r < 8; r++) {
            int i = tid + r * 256;
            int d = i >> 4, c = i & 15;
            const float4* ks = (const float4*)(Kf + (size_t)(b * D_ + d) * N_ + m0 + c * 8);
            float4 k0 = ks[0], k1 = ks[1];
            uint4 h;
            h.x = packh2(k0.x * C2, k0.y * C2);
            h.y = packh2(k0.z * C2, k0.w * C2);
            h.z = packh2(k1.x * C2, k1.y * C2);
            h.w = packh2(k1.z * C2, k1.w * C2);
            *(uint4*)(sm + SM_K + (uint32_t)(d * 256 + ((c ^ (d & 7)) << 4))) = h;
        }
    }

    auto loadQV = [&](int tile, int buf) {
        const int n0 = tile * BN;
        const uint32_t qd = sb + SM_Q + buf * 32768;
        const uint32_t vd = sb + SM_V + buf * 32768;
#pragma unroll
        for (int r = 0; r < 8; r++) {
            int i = tid + r * 256;
            int d = i >> 4, c = i & 15;
            uint32_t off = (uint32_t)(d * 256 + ((c ^ (d & 7)) << 4));
            CPA16(qd + off, (const char*)g_Qh + ((size_t)(b * D_ + d) * N_ + n0 + c * 8) * 2);
            CPA16(vd + off, (const char*)g_Vh + ((size_t)(b * D_ + d) * N_ + n0 + c * 8) * 2);
        }
    };

    // first tile = self-converted slice bx (flag already set by us; fence done)
    loadQV(bx, 0);
    CPA_COMMIT();
    CPA_WAIT0();
    __syncthreads();

    // ---- K frags (A m16k16, m-block = w) via ldmatrix.trans from [d][m] ----
    uint32_t kf[8][4];
    {
        const int drow = (g >> 1) * 8 + sx;
        const uint32_t coff = (uint32_t)((((2 * w + (g & 1)) ^ sx) & 15) << 4);
#pragma unroll
        for (int kc = 0; kc < 8; kc++)
            ldmx4t(kf[kc], sb + SM_K + (uint32_t)((kc * 16 + drow) * 256) + coff);
    }

    float ob[16][4];
#pragma unroll
    for (int i = 0; i < 16; i++)
#pragma unroll
        for (int j = 0; j < 4; j++) ob[i][j] = 0.0f;

    const int qrow  = (g & 1) * 8 + sx;   // Q trans-tile d-row offset
    const int qcoff = g >> 1;             // Q chunk parity
    const int rL    = sx + ((lane >> 4) << 3);  // V ldmatrix row
    const int cp_   = g & 1;              // V chunk parity

    for (int it = 0; it < NITER; it++) {
        const int buf = it & 1;
        if (it + 1 < NITER) {
            const int ntile = (bx + it + 1) & 15;
            // wait for producer CTA of that slice
            if (tid == 0) {
                while (atomicAdd(&g_flags[b * 16 + ntile], 0) == 0) {}
            }
            __syncthreads();
            __threadfence();
            loadQV(ntile, buf ^ 1);
            CPA_COMMIT();
        }

        const uint32_t qbuf = sb + SM_Q + buf * 32768;
        const uint32_t vbuf = sb + SM_V + buf * 32768;

        // MMA1 (f16 acc) on a 32-n chunk ci
        auto do_mma1 = [&](int ci, uint32_t (&sc)[4][2]) {
#pragma unroll
            for (int nj = 0; nj < 4; nj++) { sc[nj][0] = 0u; sc[nj][1] = 0u; }
#pragma unroll
            for (int kc = 0; kc < 8; kc++) {
                uint32_t qb8[8];
                const uint32_t qr = qbuf + (uint32_t)((kc * 16 + qrow) * 256);
                ldmx4t(&qb8[0], qr + (uint32_t)((((4 * ci + qcoff)     ^ sx) & 15) << 4));
                ldmx4t(&qb8[4], qr + (uint32_t)((((4 * ci + 2 + qcoff) ^ sx) & 15) << 4));
                mma16816h(sc[0], kf[kc], &qb8[0]);
                mma16816h(sc[1], kf[kc], &qb8[2]);
                mma16816h(sc[2], kf[kc], &qb8[4]);
                mma16816h(sc[3], kf[kc], &qb8[6]);
            }
        };
        // MMA2 (f32 acc) on chunk ci with P frags
        auto do_mma2 = [&](int ci, uint32_t (&p)[4][2]) {
#pragma unroll
            for (int kcl = 0; kcl < 2; kcl++) {
                const int cv = 4 * ci + 2 * kcl + cp_;
                const uint32_t swz = (uint32_t)(((cv ^ sx) & 15) << 4);
                uint32_t a[4] = { p[2 * kcl][0], p[2 * kcl][1],
                                  p[2 * kcl + 1][0], p[2 * kcl + 1][1] };
#pragma unroll
                for (int j = 0; j < 8; j++) {
                    uint32_t vb[4];
                    ldmx4(vb, vbuf + (uint32_t)(rL * 256 + j * 4096) + swz);
                    mma16816(ob[2 * j],     a, &vb[0]);
                    mma16816(ob[2 * j + 1], a, &vb[2]);
                }
            }
        };

        // pipelined chunks: MMA1(c+1) overlaps sig(c)+MMA2(c)
        uint32_t sc[2][4][2];
        do_mma1(0, sc[0]);
#pragma unroll
        for (int ci = 0; ci < 4; ci++) {
            if (ci < 3) do_mma1(ci + 1, sc[(ci + 1) & 1]);
            uint32_t p[4][2];
            uint32_t (&s)[4][2] = sc[ci & 1];
#pragma unroll
            for (int nj = 0; nj < 4; nj++) {
                float2 f0 = uph2(s[nj][0]);
                float2 f1 = uph2(s[nj][1]);
                p[nj][0] = packh2(sigf(f0.x), sigf(f0.y));
                p[nj][1] = packh2(sigf(f1.x), sigf(f1.y));
            }
            do_mma2(ci, p);
        }

        CPA_WAIT0();
        __syncthreads();
    }

    // ---- epilogue: O'[m,v] -> O[b][v][m0+m] ----
    float* Ob = O + (size_t)b * D_ * N_ + m0;
    const int r  = w * 16 + (lane >> 2);
    const int c0 = 2 * (lane & 3);
#pragma unroll
    for (int i = 0; i < 16; i++) {
        const int v = 8 * i + c0;
        Ob[(size_t)v * N_ + r]           = ob[i][0];
        Ob[(size_t)(v + 1) * N_ + r]     = ob[i][1];
        Ob[(size_t)v * N_ + r + 8]       = ob[i][2];
        Ob[(size_t)(v + 1) * N_ + r + 8] = ob[i][3];
    }
}

extern "C" void kernel_launch(void* const* d_in, const int* in_sizes, int n_in,
                              void* d_out, int out_size) {
    const float* Q = (const float*)d_in[0];
    const float* K = (const float*)d_in[1];
    const float* V = (const float*)d_in[2];
    float* O = (float*)d_out;

    // reset slice-ready flags (graph-legal memset node)
    void* flags_addr = nullptr;
    cudaGetSymbolAddress(&flags_addr, g_flags);
    cudaMemsetAsync(flags_addr, 0, sizeof(int) * B_ * 16);

    cudaFuncSetAttribute(sigattn_hmma, cudaFuncAttributeMaxDynamicSharedMemorySize, SMEM_TOTAL);
    sigattn_hmma<<<dim3(N_ / BM, B_), 256, SMEM_TOTAL>>>(Q, K, V, O);
}

// round 17
// speedup vs baseline: 1.2679x; 1.2679x over previous
#include <cuda_runtime.h>
#include <cuda_fp16.h>
#include <cstdint>

#define B_ 8
#define D_ 128
#define N_ 2048
#define NUNITS 2048   // 8 b * 16 mtiles * 16 n-iters
#define NSM 148

__device__ __align__(16) __half g_Qh[B_ * D_ * N_];  // [b][d][n]
__device__ __align__(16) __half g_Vh[B_ * D_ * N_];  // [b][v][n]

__device__ __forceinline__ uint32_t s2u(const void* p) {
    uint32_t a;
    asm("{ .reg .u64 t; cvta.to.shared.u64 t, %1; cvt.u32.u64 %0, t; }" : "=r"(a) : "l"(p));
    return a;
}

#define CPA16(dst, src) \
    asm volatile("cp.async.cg.shared.global [%0], [%1], 16;" :: "r"(dst), "l"(src))
#define CPA_COMMIT() asm volatile("cp.async.commit_group;" ::: "memory")
#define CPA_WAIT0()  asm volatile("cp.async.wait_group 0;" ::: "memory")

__device__ __forceinline__ void ldmx4(uint32_t* r, uint32_t addr) {
    asm volatile("ldmatrix.sync.aligned.m8n8.x4.shared.b16 {%0,%1,%2,%3}, [%4];"
        : "=r"(r[0]), "=r"(r[1]), "=r"(r[2]), "=r"(r[3]) : "r"(addr));
}
__device__ __forceinline__ void ldmx4t(uint32_t* r, uint32_t addr) {
    asm volatile("ldmatrix.sync.aligned.m8n8.x4.trans.shared.b16 {%0,%1,%2,%3}, [%4];"
        : "=r"(r[0]), "=r"(r[1]), "=r"(r[2]), "=r"(r[3]) : "r"(addr));
}
__device__ __forceinline__ void mma16816(float* d, const uint32_t* a, const uint32_t* b) {
    asm volatile("mma.sync.aligned.m16n8k16.row.col.f32.f16.f16.f32 "
        "{%0,%1,%2,%3}, {%4,%5,%6,%7}, {%8,%9}, {%0,%1,%2,%3};"
        : "+f"(d[0]), "+f"(d[1]), "+f"(d[2]), "+f"(d[3])
        : "r"(a[0]), "r"(a[1]), "r"(a[2]), "r"(a[3]), "r"(b[0]), "r"(b[1]));
}
__device__ __forceinline__ void mma16816h(uint32_t* d, const uint32_t* a, const uint32_t* b) {
    asm volatile("mma.sync.aligned.m16n8k16.row.col.f16.f16.f16.f16 "
        "{%0,%1}, {%2,%3,%4,%5}, {%6,%7}, {%0,%1};"
        : "+r"(d[0]), "+r"(d[1])
        : "r"(a[0]), "r"(a[1]), "r"(a[2]), "r"(a[3]), "r"(b[0]), "r"(b[1]));
}
__device__ __forceinline__ void redadd(float* p, float v) {
    asm volatile("red.global.add.f32 [%0], %1;" :: "l"(p), "f"(v) : "memory");
}

// K pre-scaled by 0.5/sqrt(128): sigmoid(S/sqrt(128)) = 0.5*tanh(x)+0.5
__device__ __forceinline__ float sigf(float x) {
    float t;
    asm("tanh.approx.f32 %0, %1;" : "=f"(t) : "f"(x));
    return fmaf(t, 0.5f, 0.5f);
}
__device__ __forceinline__ uint32_t packh2(float a, float b) {
    uint32_t r;
    asm("cvt.rn.f16x2.f32 %0, %1, %2;" : "=r"(r) : "f"(b), "f"(a));
    return r;
}
__device__ __forceinline__ float2 uph2(uint32_t u) {
    __half2 h = *reinterpret_cast<__half2*>(&u);
    return __half22float2(h);
}

// smem: K 32KB @0 | Q[2] 64KB @32K | V[2] 64KB @96K
#define SM_K 0
#define SM_Q 32768
#define SM_V 98304
#define SMEM_TOTAL 163840

__global__ __launch_bounds__(256, 1)
void sigattn_hmma(const float* __restrict__ Kf, float* __restrict__ O) {
    extern __shared__ char sm[];
    const uint32_t sb = s2u(sm);
    const int tid = threadIdx.x, w = tid >> 5, lane = tid & 31;
    const int g = lane >> 3, sx = lane & 7;
    const int c = blockIdx.x;

    const int u0 = (NUNITS * c) / NSM;
    const int u1 = (NUNITS * (c + 1)) / NSM;
    if (u0 >= u1) return;

    // per-lane constants
    const int qrow  = (g & 1) * 8 + sx;
    const int qcoff = g >> 1;
    const int rL    = sx + ((lane >> 4) << 3);
    const int cp_   = g & 1;
    const int drow  = (g >> 1) * 8 + sx;
    const uint32_t kcoff = (uint32_t)((((2 * w + (g & 1)) ^ sx) & 15) << 4);
    const int er = w * 16 + (lane >> 2);      // epilogue row
    const int ec0 = 2 * (lane & 3);

    auto loadQV = [&](int b, int n0, int buf) {
#pragma unroll
        for (int r = 0; r < 8; r++) {
            int i = tid + r * 256;
            int d = i >> 4, cc = i & 15;
            uint32_t off = (uint32_t)(d * 256 + ((cc ^ (d & 7)) << 4));
            CPA16(sb + SM_Q + buf * 32768 + off,
                  (const char*)g_Qh + ((size_t)(b * D_ + d) * N_ + n0 + cc * 8) * 2);
            CPA16(sb + SM_V + buf * 32768 + off,
                  (const char*)g_Vh + ((size_t)(b * D_ + d) * N_ + n0 + cc * 8) * 2);
        }
    };
    // K tile convert (fp32 -> scaled fp16, swizzled smem). Caller handles syncs.
    auto convK = [&](int b, int m0) {
        const float C2 = 0.5f * 0.08838834764831845f;
#pragma unroll
        for (int r = 0; r < 8; r++) {
            int i = tid + r * 256;
            int d = i >> 4, cc = i & 15;
            const float4* ks = (const float4*)(Kf + (size_t)(b * D_ + d) * N_ + m0 + cc * 8);
            float4 k0 = ks[0], k1 = ks[1];
            uint4 h;
            h.x = packh2(k0.x * C2, k0.y * C2);
            h.y = packh2(k0.z * C2, k0.w * C2);
            h.z = packh2(k1.x * C2, k1.y * C2);
            h.w = packh2(k1.z * C2, k1.w * C2);
            *(uint4*)(sm + SM_K + (uint32_t)(d * 256 + ((cc ^ (d & 7)) << 4))) = h;
        }
    };

    uint32_t kf[8][4];
    float ob[16][4];
    auto ldK = [&]() {
#pragma unroll
        for (int kc = 0; kc < 8; kc++)
            ldmx4t(kf[kc], sb + SM_K + (uint32_t)((kc * 16 + drow) * 256) + kcoff);
    };
    auto zeroOb = [&]() {
#pragma unroll
        for (int i = 0; i < 16; i++)
#pragma unroll
            for (int j = 0; j < 4; j++) ob[i][j] = 0.0f;
    };
    auto flushOb = [&](int b, int m0) {
        float* Ob = O + (size_t)b * D_ * N_ + m0;
#pragma unroll
        for (int i = 0; i < 16; i++) {
            const int v = 8 * i + ec0;
            redadd(Ob + (size_t)v * N_ + er,           ob[i][0]);
            redadd(Ob + (size_t)(v + 1) * N_ + er,     ob[i][1]);
            redadd(Ob + (size_t)v * N_ + er + 8,       ob[i][2]);
            redadd(Ob + (size_t)(v + 1) * N_ + er + 8, ob[i][3]);
        }
    };

    // ---- prologue for first unit ----
    int cur_bt = u0 >> 4;                      // (b*16 + mtile)
    {
        const int b = cur_bt >> 4, n0 = (u0 & 15) * 128;
        loadQV(b, n0, 0);
        CPA_COMMIT();
        convK(b, (cur_bt & 15) * 128);
        CPA_WAIT0();
        __syncthreads();
        ldK();
    }
    zeroOb();

    for (int u = u0; u < u1; u++) {
        const int buf = (u - u0) & 1;
        const int bt = u >> 4;
        const int b = bt >> 4;
        if (u + 1 < u1) {
            const int nb = (u + 1) >> 8;       // next unit's batch
            loadQV(nb, ((u + 1) & 15) * 128, buf ^ 1);
            CPA_COMMIT();
        }

        const uint32_t qbuf = sb + SM_Q + buf * 32768;
        const uint32_t vbuf = sb + SM_V + buf * 32768;

        auto do_mma1 = [&](int ci, uint32_t (&sc)[4][2]) {
#pragma unroll
            for (int nj = 0; nj < 4; nj++) { sc[nj][0] = 0u; sc[nj][1] = 0u; }
#pragma unroll
            for (int kc = 0; kc < 8; kc++) {
                uint32_t qb8[8];
                const uint32_t qr = qbuf + (uint32_t)((kc * 16 + qrow) * 256);
                ldmx4t(&qb8[0], qr + (uint32_t)((((4 * ci + qcoff)     ^ sx) & 15) << 4));
                ldmx4t(&qb8[4], qr + (uint32_t)((((4 * ci + 2 + qcoff) ^ sx) & 15) << 4));
                mma16816h(sc[0], kf[kc], &qb8[0]);
                mma16816h(sc[1], kf[kc], &qb8[2]);
                mma16816h(sc[2], kf[kc], &qb8[4]);
                mma16816h(sc[3], kf[kc], &qb8[6]);
            }
        };
        auto do_mma2 = [&](int ci, uint32_t (&p)[4][2]) {
#pragma unroll
            for (int kcl = 0; kcl < 2; kcl++) {
                const int cv = 4 * ci + 2 * kcl + cp_;
                const uint32_t swz = (uint32_t)(((cv ^ sx) & 15) << 4);
                uint32_t a[4] = { p[2 * kcl][0], p[2 * kcl][1],
                                  p[2 * kcl + 1][0], p[2 * kcl + 1][1] };
#pragma unroll
                for (int j = 0; j < 8; j++) {
                    uint32_t vb[4];
                    ldmx4(vb, vbuf + (uint32_t)(rL * 256 + j * 4096) + swz);
                    mma16816(ob[2 * j],     a, &vb[0]);
                    mma16816(ob[2 * j + 1], a, &vb[2]);
                }
            }
        };

        uint32_t sc[2][4][2];
        do_mma1(0, sc[0]);
#pragma unroll
        for (int ci = 0; ci < 4; ci++) {
            if (ci < 3) do_mma1(ci + 1, sc[(ci + 1) & 1]);
            uint32_t p[4][2];
            uint32_t (&s)[4][2] = sc[ci & 1];
#pragma unroll
            for (int nj = 0; nj < 4; nj++) {
                float2 f0 = uph2(s[nj][0]);
                float2 f1 = uph2(s[nj][1]);
                p[nj][0] = packh2(sigf(f0.x), sigf(f0.y));
                p[nj][1] = packh2(sigf(f1.x), sigf(f1.y));
            }
            do_mma2(ci, p);
        }

        CPA_WAIT0();
        __syncthreads();

        // segment boundary: flush accumulators, rebuild K tile
        const int nbt = (u + 1 < u1) ? ((u + 1) >> 4) : -1;
        if (nbt != cur_bt) {
            flushOb(b, (cur_bt & 15) * 128);
            zeroOb();
            if (nbt >= 0) {
                convK(nbt >> 4, (nbt & 15) * 128);
                __syncthreads();
                ldK();
                cur_bt = nbt;
            }
        }
    }
}

// ---- preprocess: fp32 -> fp16 cast for Q and V only ----
__global__ void prep_cast(const float* __restrict__ Q, const float* __restrict__ V) {
    int i = blockIdx.x * 256 + threadIdx.x;
    const float* src = (blockIdx.y == 0) ? Q : V;
    __half* dst = (blockIdx.y == 0) ? g_Qh : g_Vh;
    float4 v = ((const float4*)src)[i];
    __half2* o = (__half2*)dst;
    o[2 * i]     = __floats2half2_rn(v.x, v.y);
    o[2 * i + 1] = __floats2half2_rn(v.z, v.w);
}

extern "C" void kernel_launch(void* const* d_in, const int* in_sizes, int n_in,
                              void* d_out, int out_size) {
    const float* Q = (const float*)d_in[0];
    const float* K = (const float*)d_in[1];
    const float* V = (const float*)d_in[2];
    float* O = (float*)d_out;

    // O accumulated via red.add — zero it (graph-legal memset node)
    cudaMemsetAsync(d_out, 0, (size_t)out_size * sizeof(float));
    prep_cast<<<dim3((B_ * D_ * N_ / 4) / 256, 2), 256>>>(Q, V);

    cudaFuncSetAttribute(sigattn_hmma, cudaFuncAttributeMaxDynamicSharedMemorySize, SMEM_TOTAL);
    sigattn_hmma<<<NSM, 256, SMEM_TOTAL>>>(K, O);
}